// round 3
// baseline (speedup 1.0000x reference)
#include <cuda_runtime.h>
#include <cuda_bf16.h>
#include <cstdint>

// ============================================================================
// MoE top-2 (E=8, H=1024, I=2048) — portable-PTX (compute_100) implementation.
// tcgen05 is unavailable (harness emits compute_100 PTX), so GEMMs use
// mma.sync.m16n8k8 TF32 with cp.async staging.
//   1) router: fp32 logits, top-2, softmax (+ router_logits output)
//   2) deterministic per-expert compaction
//   3) GEMM1: h = gelu(x_gathered @ w1^T + b1)
//   4) GEMM2: out += wt * (h @ w2^T + b2)   (scatter atomicAdd, 2 adds/elem)
// ============================================================================

#define HID    1024
#define INTERD 2048
#define NEXP   8
#define MAXT   16384

#define BM 128
#define BN 256
#define BK 32
#define ROWF 36                      // padded row stride in floats (conflict-free)
#define ASZ_BYTES   (BM * ROWF * 4)              // 18432
#define STAGE_BYTES ((BM + BN) * ROWF * 4)       // 55296
#define NSTAGE 3
#define SMEM_BYTES (NSTAGE * STAGE_BYTES)        // 165888

#define SQRT1_2 0.70710678118654752440f

// ---------------- device scratch -------------------------------------------
__device__ int    g_topk_idx[MAXT * 2];
__device__ float  g_topk_w[MAXT * 2];
__device__ int    g_count[NEXP];
__device__ int    g_base[NEXP];
__device__ int    g_slot_tok[MAXT * 2];
__device__ float  g_slot_wt[MAXT * 2];
__device__ float  g_h[(size_t)MAXT * 2 * INTERD];   // 256 MB intermediate

// ---------------- helpers ---------------------------------------------------
__device__ __forceinline__ uint32_t smem_to_u32(const void* p) {
    uint32_t a;
    asm("{ .reg .u64 t; cvta.to.shared.u64 t, %1; cvt.u32.u64 %0, t; }"
        : "=r"(a) : "l"(p));
    return a;
}

__device__ __forceinline__ float lds_f(uint32_t a) {
    float v;
    asm("ld.shared.f32 %0, [%1];" : "=f"(v) : "r"(a));
    return v;
}

__device__ __forceinline__ uint32_t f2tf(float f) {
    uint32_t r;
    asm("cvt.rna.tf32.f32 %0, %1;" : "=r"(r) : "f"(f));
    return r;
}

#define CP16(dst, src) \
    asm volatile("cp.async.cg.shared.global [%0], [%1], 16;" \
                 :: "r"(dst), "l"(src))

__device__ __forceinline__ void mma8(float* c, const uint32_t* a,
                                     const uint32_t* b) {
    asm volatile(
        "mma.sync.aligned.m16n8k8.row.col.f32.tf32.tf32.f32 "
        "{%0,%1,%2,%3}, {%4,%5,%6,%7}, {%8,%9}, {%0,%1,%2,%3};"
        : "+f"(c[0]), "+f"(c[1]), "+f"(c[2]), "+f"(c[3])
        : "r"(a[0]), "r"(a[1]), "r"(a[2]), "r"(a[3]),
          "r"(b[0]), "r"(b[1]));
}

// ---------------- kernel 1: router ------------------------------------------
__global__ void __launch_bounds__(256)
router_kernel(const float* __restrict__ x, const float* __restrict__ gate,
              float* rlog, int T) {
    __shared__ float sg[NEXP * HID];
    for (int i = threadIdx.x; i < NEXP * HID; i += 256) sg[i] = gate[i];
    __syncthreads();

    const int wid = threadIdx.x >> 5, lid = threadIdx.x & 31;
    const int t = blockIdx.x * 8 + wid;
    if (t >= T) return;

    const float4* xr = reinterpret_cast<const float4*>(x + (size_t)t * HID);
    const float4* g4 = reinterpret_cast<const float4*>(sg);
    float acc[NEXP];
#pragma unroll
    for (int e = 0; e < NEXP; e++) acc[e] = 0.0f;
#pragma unroll
    for (int i = 0; i < 8; i++) {
        float4 xv = xr[lid + i * 32];
#pragma unroll
        for (int e = 0; e < NEXP; e++) {
            float4 gv = g4[e * 256 + lid + i * 32];
            acc[e] += xv.x * gv.x + xv.y * gv.y + xv.z * gv.z + xv.w * gv.w;
        }
    }
#pragma unroll
    for (int e = 0; e < NEXP; e++)
#pragma unroll
        for (int o = 16; o > 0; o >>= 1)
            acc[e] += __shfl_down_sync(0xffffffffu, acc[e], o);

    if (lid == 0) {
        if (rlog) {
#pragma unroll
            for (int e = 0; e < NEXP; e++) rlog[(size_t)t * NEXP + e] = acc[e];
        }
        float l0 = -3.4e38f; int i0 = 0;
#pragma unroll
        for (int e = 0; e < NEXP; e++)
            if (acc[e] > l0) { l0 = acc[e]; i0 = e; }
        float l1 = -3.4e38f; int i1 = 0;
#pragma unroll
        for (int e = 0; e < NEXP; e++)
            if (e != i0 && acc[e] > l1) { l1 = acc[e]; i1 = e; }
        float s1 = expf(l1 - l0);
        float inv = 1.0f / (1.0f + s1);
        g_topk_idx[2 * t] = i0;  g_topk_idx[2 * t + 1] = i1;
        g_topk_w[2 * t] = inv;   g_topk_w[2 * t + 1] = s1 * inv;
    }
}

// ---------------- kernels 2-4: deterministic compaction ---------------------
__global__ void __launch_bounds__(256) count_kernel(int T) {
    __shared__ int red[256];
    const int e = blockIdx.x;
    int c = 0;
    for (int t = threadIdx.x; t < T; t += 256)
        c += (g_topk_idx[2 * t] == e) + (g_topk_idx[2 * t + 1] == e);
    red[threadIdx.x] = c;
    __syncthreads();
    for (int s = 128; s > 0; s >>= 1) {
        if (threadIdx.x < s) red[threadIdx.x] += red[threadIdx.x + s];
        __syncthreads();
    }
    if (threadIdx.x == 0) g_count[e] = red[0];
}

__global__ void base_kernel() {
    int r = 0;
    for (int e = 0; e < NEXP; e++) { g_base[e] = r; r += g_count[e]; }
}

__global__ void __launch_bounds__(256) compact_kernel(int T) {
    const int e = blockIdx.x;
    __shared__ int wcnt[8];
    __shared__ int s_running;
    const int tid = threadIdx.x, wid = tid >> 5, lid = tid & 31;
    if (tid == 0) s_running = g_base[e];
    __syncthreads();
    for (int t0 = 0; t0 < T; t0 += 256) {
        const int t = t0 + tid;
        int f = 0; float w = 0.0f;
        if (t < T) {
            int i0 = g_topk_idx[2 * t], i1 = g_topk_idx[2 * t + 1];
            if (i0 == e)      { f = 1; w = g_topk_w[2 * t]; }
            else if (i1 == e) { f = 1; w = g_topk_w[2 * t + 1]; }
        }
        unsigned mask = __ballot_sync(0xffffffffu, f);
        if (lid == 0) wcnt[wid] = __popc(mask);
        __syncthreads();
        int prefix = 0, total = 0;
#pragma unroll
        for (int wI = 0; wI < 8; wI++) {
            if (wI < wid) prefix += wcnt[wI];
            total += wcnt[wI];
        }
        const int runbase = s_running;
        if (f) {
            int pos = runbase + prefix + __popc(mask & ((1u << lid) - 1u));
            g_slot_tok[pos] = t;
            g_slot_wt[pos]  = w;
        }
        __syncthreads();
        if (tid == 0) s_running = runbase + total;
        __syncthreads();
    }
}

// ---------------- grouped GEMM (mma.sync tf32) ------------------------------
// CTA tile 128x256, BK=32, 8 warps of 64x64.  FIRST: A = gathered x rows,
// epilogue = bias+gelu -> g_h.  !FIRST: A = g_h rows, epilogue =
// (acc+bias)*wt scatter-atomicAdd into out.
template <int K, int NTOT, bool FIRST>
__global__ void __launch_bounds__(256)
moe_gemm_kernel(const float* __restrict__ A_in,
                const float* __restrict__ W,
                const float* __restrict__ bias,
                float* __restrict__ out) {
    const int e = blockIdx.z;
    const int cnt = g_count[e];
    const int mtile = blockIdx.y;
    if (mtile * BM >= cnt) return;
    const int ntile = blockIdx.x;
    const int base = g_base[e];

    extern __shared__ float smem[];
    const uint32_t smem_u = smem_to_u32(smem);

    const int tid = threadIdx.x;
    const int wid = tid >> 5, lid = tid & 31;
    const int gid = lid >> 2, tig = lid & 3;
    const int m_off = (wid >> 2) * 64;
    const int n_off = (wid & 3) * 64;

    // ---- staging geometry: thread copies 4 A-chunks + 8 B-chunks / stage ---
    const int r = tid >> 3, seg = tid & 7;          // row group, 16B segment
    const float* Abase = FIRST ? A_in : (const float*)g_h;
    const float* aptr[4];
#pragma unroll
    for (int j = 0; j < 4; j++) {
        int grow = mtile * BM + r + 32 * j;
        grow = (grow < cnt) ? grow : (cnt - 1);
        int arow = FIRST ? g_slot_tok[base + grow] : (base + grow);
        aptr[j] = Abase + (size_t)arow * K + seg * 4;
    }
    const float* bptr =
        W + ((size_t)e * NTOT + ntile * BN + r) * K + seg * 4;
    const uint32_t a0 = (uint32_t)(r * ROWF + seg * 4) * 4u;
    const uint32_t b0 = (uint32_t)ASZ_BYTES + a0;

#define LOAD_STAGE(buf, koff) do { \
        uint32_t _s = smem_u + (uint32_t)(buf) * STAGE_BYTES; \
        _Pragma("unroll") \
        for (int _j = 0; _j < 4; _j++) \
            CP16(_s + a0 + _j * (32 * ROWF * 4), aptr[_j] + (koff)); \
        _Pragma("unroll") \
        for (int _j = 0; _j < 8; _j++) \
            CP16(_s + b0 + _j * (32 * ROWF * 4), \
                 bptr + (koff) + (size_t)_j * 32 * K); \
        asm volatile("cp.async.commit_group;" ::: "memory"); \
    } while (0)

    float acc[4][8][4];
#pragma unroll
    for (int i = 0; i < 4; i++)
#pragma unroll
        for (int j = 0; j < 8; j++)
#pragma unroll
            for (int q = 0; q < 4; q++) acc[i][j][q] = 0.0f;

    constexpr int NK = K / BK;
    LOAD_STAGE(0, 0);
    LOAD_STAGE(1, BK);

    int buf = 0;
#pragma unroll 1
    for (int it = 0; it < NK; it++) {
        if (it == NK - 1)
            asm volatile("cp.async.wait_group 0;" ::: "memory");
        else
            asm volatile("cp.async.wait_group 1;" ::: "memory");
        __syncthreads();
        if (it + 2 < NK) {
            int nb = buf + 2; if (nb >= NSTAGE) nb -= NSTAGE;
            LOAD_STAGE(nb, (it + 2) * BK);
        }

        const uint32_t sa = smem_u + (uint32_t)buf * STAGE_BYTES;
        const uint32_t aB = sa + (uint32_t)((m_off + gid) * ROWF + tig) * 4u;
        const uint32_t bB = sa + ASZ_BYTES
                          + (uint32_t)((n_off + gid) * ROWF + tig) * 4u;
#pragma unroll
        for (int kk = 0; kk < 4; kk++) {
            uint32_t av[4][4];
#pragma unroll
            for (int i = 0; i < 4; i++) {
                uint32_t ad = aB + (uint32_t)(i * 16 * ROWF * 4) + kk * 32;
                av[i][0] = f2tf(lds_f(ad));
                av[i][1] = f2tf(lds_f(ad + 8 * ROWF * 4));
                av[i][2] = f2tf(lds_f(ad + 16));
                av[i][3] = f2tf(lds_f(ad + 8 * ROWF * 4 + 16));
            }
            uint32_t bv[8][2];
#pragma unroll
            for (int j = 0; j < 8; j++) {
                uint32_t bd = bB + (uint32_t)(j * 8 * ROWF * 4) + kk * 32;
                bv[j][0] = f2tf(lds_f(bd));
                bv[j][1] = f2tf(lds_f(bd + 16));
            }
#pragma unroll
            for (int i = 0; i < 4; i++)
#pragma unroll
                for (int j = 0; j < 8; j++)
                    mma8(acc[i][j], av[i], bv[j]);
        }
        buf++; if (buf >= NSTAGE) buf = 0;
    }
#undef LOAD_STAGE

    // ---- epilogue ----------------------------------------------------------
    const int cbase = ntile * BN + n_off + 2 * tig;
    float2 bv2[8];
#pragma unroll
    for (int j = 0; j < 8; j++) {
        bv2[j].x = bias[(size_t)e * NTOT + cbase + j * 8];
        bv2[j].y = bias[(size_t)e * NTOT + cbase + j * 8 + 1];
    }

#pragma unroll
    for (int i = 0; i < 4; i++) {
#pragma unroll
        for (int h = 0; h < 2; h++) {
            const int lrow = m_off + i * 16 + gid + h * 8;
            const int grow = mtile * BM + lrow;
            if (grow >= cnt) continue;
            if (FIRST) {
                float* dst = g_h + (size_t)(base + grow) * NTOT + cbase;
#pragma unroll
                for (int j = 0; j < 8; j++) {
                    float v0 = acc[i][j][h * 2]     + bv2[j].x;
                    float v1 = acc[i][j][h * 2 + 1] + bv2[j].y;
                    float g0 = 0.5f * v0 * (1.0f + erff(v0 * SQRT1_2));
                    float g1 = 0.5f * v1 * (1.0f + erff(v1 * SQRT1_2));
                    *reinterpret_cast<float2*>(dst + j * 8) =
                        make_float2(g0, g1);
                }
            } else {
                const int tok = g_slot_tok[base + grow];
                const float wt = g_slot_wt[base + grow];
                float* dst = out + (size_t)tok * NTOT + cbase;
#pragma unroll
                for (int j = 0; j < 8; j++) {
                    atomicAdd(dst + j * 8,
                              (acc[i][j][h * 2] + bv2[j].x) * wt);
                    atomicAdd(dst + j * 8 + 1,
                              (acc[i][j][h * 2 + 1] + bv2[j].y) * wt);
                }
            }
        }
    }
}

// ---------------- host launcher ---------------------------------------------
extern "C" void kernel_launch(void* const* d_in, const int* in_sizes, int n_in,
                              void* d_out, int out_size) {
    const float* x    = (const float*)d_in[0];
    const float* gate = (const float*)d_in[1];
    const float* w1   = (const float*)d_in[2];
    const float* b1   = (const float*)d_in[3];
    const float* w2   = (const float*)d_in[4];
    const float* b2   = (const float*)d_in[5];

    const int T = in_sizes[0] / HID;
    float* out = (float*)d_out;
    float* rlog = ((size_t)out_size >= (size_t)T * HID + (size_t)T * NEXP)
                      ? out + (size_t)T * HID : nullptr;

    cudaFuncSetAttribute(moe_gemm_kernel<HID, INTERD, true>,
                         cudaFuncAttributeMaxDynamicSharedMemorySize,
                         SMEM_BYTES);
    cudaFuncSetAttribute(moe_gemm_kernel<INTERD, HID, false>,
                         cudaFuncAttributeMaxDynamicSharedMemorySize,
                         SMEM_BYTES);

    cudaMemsetAsync(d_out, 0, (size_t)T * HID * sizeof(float));

    router_kernel<<<(T + 7) / 8, 256>>>(x, gate, rlog, T);
    count_kernel<<<NEXP, 256>>>(T);
    base_kernel<<<1, 1>>>();
    compact_kernel<<<NEXP, 256>>>(T);

    const int mtiles = (T + BM - 1) / BM;   // worst case: all tokens one expert
    moe_gemm_kernel<HID, INTERD, true>
        <<<dim3(INTERD / BN, mtiles, NEXP), 256, SMEM_BYTES>>>(
            x, w1, b1, nullptr);
    moe_gemm_kernel<INTERD, HID, false>
        <<<dim3(HID / BN, mtiles, NEXP), 256, SMEM_BYTES>>>(
            nullptr, w2, b2, out);
}

// round 7
// speedup vs baseline: 1.1300x; 1.1300x over previous
#include <cuda_runtime.h>
#include <cuda_bf16.h>
#include <cstdint>

// ============================================================================
// MoE top-2 (E=8, H=1024, I=2048) — portable-PTX (compute_100) implementation.
// GEMMs: mma.sync.m16n8k8 TF32, ldmatrix.x4 fragment loads + register-side
// cvt.rna.tf32, cp.async 3-stage pipeline (R3-proven footprint: no extra
// device statics, no spill-prone register growth).
// ============================================================================

#define HID    1024
#define INTERD 2048
#define NEXP   8
#define MAXT   16384

#define BM 128
#define BN 256
#define BK 32
#define ROWF 36                      // padded row stride in floats (conflict-free)
#define ASZ_BYTES   (BM * ROWF * 4)              // 18432
#define STAGE_BYTES ((BM + BN) * ROWF * 4)       // 55296
#define NSTAGE 3
#define SMEM_BYTES (NSTAGE * STAGE_BYTES)        // 165888

#define SQRT1_2 0.70710678118654752440f

// ---------------- device scratch (same footprint as passing R3) -------------
__device__ int    g_topk_idx[MAXT * 2];
__device__ float  g_topk_w[MAXT * 2];
__device__ int    g_count[NEXP];
__device__ int    g_slot_tok[MAXT * 2];
__device__ float  g_slot_wt[MAXT * 2];
__device__ float  g_h[(size_t)MAXT * 2 * INTERD];   // 256 MB intermediate

// ---------------- helpers ---------------------------------------------------
__device__ __forceinline__ uint32_t smem_to_u32(const void* p) {
    uint32_t a;
    asm("{ .reg .u64 t; cvta.to.shared.u64 t, %1; cvt.u32.u64 %0, t; }"
        : "=r"(a) : "l"(p));
    return a;
}

__device__ __forceinline__ uint32_t f2tf(float f) {
    uint32_t r;
    asm("cvt.rna.tf32.f32 %0, %1;" : "=r"(r) : "f"(f));
    return r;
}

// round a raw-fp32-bit register to tf32 in place
__device__ __forceinline__ void tfr(uint32_t& v) {
    v = f2tf(__uint_as_float(v));
}

#define CP16(dst, src) \
    asm volatile("cp.async.cg.shared.global [%0], [%1], 16;" \
                 :: "r"(dst), "l"(src))

#define LDSM_X4(r0, r1, r2, r3, addr) \
    asm volatile("ldmatrix.sync.aligned.m8n8.x4.shared.b16 {%0,%1,%2,%3}, [%4];" \
                 : "=r"(r0), "=r"(r1), "=r"(r2), "=r"(r3) : "r"(addr))

__device__ __forceinline__ void mma8(float* c, const uint32_t* a,
                                     const uint32_t* b) {
    asm volatile(
        "mma.sync.aligned.m16n8k8.row.col.f32.tf32.tf32.f32 "
        "{%0,%1,%2,%3}, {%4,%5,%6,%7}, {%8,%9}, {%0,%1,%2,%3};"
        : "+f"(c[0]), "+f"(c[1]), "+f"(c[2]), "+f"(c[3])
        : "r"(a[0]), "r"(a[1]), "r"(a[2]), "r"(a[3]),
          "r"(b[0]), "r"(b[1]));
}

// ---------------- kernel 1: router (also zeroes g_count) --------------------
__global__ void __launch_bounds__(256)
router_kernel(const float* __restrict__ x, const float* __restrict__ gate,
              float* rlog, int T) {
    if (blockIdx.x == 0 && threadIdx.x < NEXP) g_count[threadIdx.x] = 0;
    __shared__ float sg[NEXP * HID];
    for (int i = threadIdx.x; i < NEXP * HID; i += 256) sg[i] = gate[i];
    __syncthreads();

    const int wid = threadIdx.x >> 5, lid = threadIdx.x & 31;
    const int t = blockIdx.x * 8 + wid;
    if (t >= T) return;

    const float4* xr = reinterpret_cast<const float4*>(x + (size_t)t * HID);
    const float4* g4 = reinterpret_cast<const float4*>(sg);
    float acc[NEXP];
#pragma unroll
    for (int e = 0; e < NEXP; e++) acc[e] = 0.0f;
#pragma unroll
    for (int i = 0; i < 8; i++) {
        float4 xv = xr[lid + i * 32];
#pragma unroll
        for (int e = 0; e < NEXP; e++) {
            float4 gv = g4[e * 256 + lid + i * 32];
            acc[e] += xv.x * gv.x + xv.y * gv.y + xv.z * gv.z + xv.w * gv.w;
        }
    }
#pragma unroll
    for (int e = 0; e < NEXP; e++)
#pragma unroll
        for (int o = 16; o > 0; o >>= 1)
            acc[e] += __shfl_down_sync(0xffffffffu, acc[e], o);

    if (lid == 0) {
        if (rlog) {
#pragma unroll
            for (int e = 0; e < NEXP; e++) rlog[(size_t)t * NEXP + e] = acc[e];
        }
        float l0 = -3.4e38f; int i0 = 0;
#pragma unroll
        for (int e = 0; e < NEXP; e++)
            if (acc[e] > l0) { l0 = acc[e]; i0 = e; }
        float l1 = -3.4e38f; int i1 = 0;
#pragma unroll
        for (int e = 0; e < NEXP; e++)
            if (e != i0 && acc[e] > l1) { l1 = acc[e]; i1 = e; }
        float s1 = expf(l1 - l0);
        float inv = 1.0f / (1.0f + s1);
        g_topk_idx[2 * t] = i0;  g_topk_idx[2 * t + 1] = i1;
        g_topk_w[2 * t] = inv;   g_topk_w[2 * t + 1] = s1 * inv;
    }
}

// ---------------- kernels 2-3: deterministic compaction ---------------------
__global__ void __launch_bounds__(256) count_kernel(int T) {
    __shared__ int sc[NEXP];
    if (threadIdx.x < NEXP) sc[threadIdx.x] = 0;
    __syncthreads();
    const int stride = gridDim.x * blockDim.x;
    for (int t = blockIdx.x * blockDim.x + threadIdx.x; t < T; t += stride) {
        atomicAdd(&sc[g_topk_idx[2 * t]], 1);
        atomicAdd(&sc[g_topk_idx[2 * t + 1]], 1);
    }
    __syncthreads();
    if (threadIdx.x < NEXP) atomicAdd(&g_count[threadIdx.x], sc[threadIdx.x]);
}

__global__ void __launch_bounds__(1024) compact_kernel(int T) {
    const int e = blockIdx.x;
    __shared__ int wcnt[32];
    __shared__ int s_run;
    const int tid = threadIdx.x, wid = tid >> 5, lid = tid & 31;
    if (tid == 0) {
        int b = 0;
        for (int ee = 0; ee < e; ee++) b += g_count[ee];
        s_run = b;
    }
    __syncthreads();
    for (int t0 = 0; t0 < T; t0 += 1024) {
        const int t = t0 + tid;
        int f = 0; float w = 0.0f;
        if (t < T) {
            int i0 = g_topk_idx[2 * t], i1 = g_topk_idx[2 * t + 1];
            if (i0 == e)      { f = 1; w = g_topk_w[2 * t]; }
            else if (i1 == e) { f = 1; w = g_topk_w[2 * t + 1]; }
        }
        unsigned mask = __ballot_sync(0xffffffffu, f);
        if (lid == 0) wcnt[wid] = __popc(mask);
        __syncthreads();
        if (wid == 0) {                       // inclusive scan of 32 warp counts
            int v = wcnt[lid];
#pragma unroll
            for (int o = 1; o < 32; o <<= 1) {
                int u = __shfl_up_sync(0xffffffffu, v, o);
                if (lid >= o) v += u;
            }
            wcnt[lid] = v;
        }
        __syncthreads();
        const int run = s_run;
        const int pre = (wid ? wcnt[wid - 1] : 0);
        const int total = wcnt[31];
        if (f) {
            int pos = run + pre + __popc(mask & ((1u << lid) - 1u));
            g_slot_tok[pos] = t;
            g_slot_wt[pos]  = w;
        }
        __syncthreads();
        if (tid == 0) s_run = run + total;
        __syncthreads();
    }
}

// ---------------- grouped GEMM (mma.sync tf32, ldmatrix) --------------------
// CTA tile 128x256, BK=32, 8 warps of 64x64; 3-stage cp.async pipeline.
// Fragments loaded with ldmatrix.x4 and rounded to tf32 in registers.
// FIRST: A = gathered x rows, epilogue bias+gelu -> g_h.
// !FIRST: A = g_h rows, epilogue (acc+bias)*wt scatter-atomicAdd.
template <int K, int NTOT, bool FIRST>
__global__ void __launch_bounds__(256, 1)
moe_gemm_kernel(const float* __restrict__ A_in,
                const float* __restrict__ W,
                const float* __restrict__ bias,
                float* __restrict__ out) {
    const int e = blockIdx.z;
    const int cnt = g_count[e];
    const int mtile = blockIdx.y;
    if (mtile * BM >= cnt) return;
    const int ntile = blockIdx.x;
    int base = 0;
    for (int ee = 0; ee < e; ee++) base += g_count[ee];

    extern __shared__ float smem[];
    const uint32_t smem_u = smem_to_u32(smem);

    const int tid = threadIdx.x;
    const int wid = tid >> 5, lid = tid & 31;
    const int gid = lid >> 2, tig = lid & 3;
    const int m_off = (wid >> 2) * 64;
    const int n_off = (wid & 3) * 64;

    // ldmatrix per-lane base offsets (bytes, within stage)
    const uint32_t aLane =
        (uint32_t)((m_off + (lid & 15)) * ROWF) * 4u + ((lid & 16) ? 16u : 0u);
    const uint32_t bLane = (uint32_t)ASZ_BYTES
        + (uint32_t)((n_off + ((lid & 16) ? 8 : 0) + (lid & 7)) * ROWF) * 4u
        + ((lid & 8) ? 16u : 0u);

    // ---- staging geometry: thread copies 4 A-chunks + 8 B-chunks / stage ---
    const int r = tid >> 3, seg = tid & 7;          // row group, 16B segment
    const float* Abase = FIRST ? A_in : (const float*)g_h;
    const float* aptr[4];
#pragma unroll
    for (int j = 0; j < 4; j++) {
        int grow = mtile * BM + r + 32 * j;
        grow = (grow < cnt) ? grow : (cnt - 1);
        int arow = FIRST ? g_slot_tok[base + grow] : (base + grow);
        aptr[j] = Abase + (size_t)arow * K + seg * 4;
    }
    const float* bptr =
        W + ((size_t)e * NTOT + ntile * BN + r) * K + seg * 4;
    const uint32_t a0 = (uint32_t)(r * ROWF + seg * 4) * 4u;
    const uint32_t b0 = (uint32_t)ASZ_BYTES + a0;

#define LOAD_STAGE(buf, koff) do { \
        uint32_t _s = smem_u + (uint32_t)(buf) * STAGE_BYTES; \
        _Pragma("unroll") \
        for (int _j = 0; _j < 4; _j++) \
            CP16(_s + a0 + _j * (32 * ROWF * 4), aptr[_j] + (koff)); \
        _Pragma("unroll") \
        for (int _j = 0; _j < 8; _j++) \
            CP16(_s + b0 + _j * (32 * ROWF * 4), \
                 bptr + (koff) + (size_t)_j * 32 * K); \
        asm volatile("cp.async.commit_group;" ::: "memory"); \
    } while (0)

    float acc[4][8][4];
#pragma unroll
    for (int i = 0; i < 4; i++)
#pragma unroll
        for (int j = 0; j < 8; j++)
#pragma unroll
            for (int q = 0; q < 4; q++) acc[i][j][q] = 0.0f;

    constexpr int NK = K / BK;
    LOAD_STAGE(0, 0);
    LOAD_STAGE(1, BK);

    int buf = 0;
#pragma unroll 1
    for (int it = 0; it < NK; it++) {
        if (it == NK - 1)
            asm volatile("cp.async.wait_group 0;" ::: "memory");
        else
            asm volatile("cp.async.wait_group 1;" ::: "memory");
        __syncthreads();
        if (it + 2 < NK) {
            int nb = buf + 2; if (nb >= NSTAGE) nb -= NSTAGE;
            LOAD_STAGE(nb, (it + 2) * BK);
        }

        const uint32_t sa = smem_u + (uint32_t)buf * STAGE_BYTES;
        const uint32_t aB = sa + aLane;
        const uint32_t bB = sa + bLane;
#pragma unroll
        for (int kk = 0; kk < 4; kk++) {
            uint32_t av[4][4];
#pragma unroll
            for (int i = 0; i < 4; i++) {
                LDSM_X4(av[i][0], av[i][1], av[i][2], av[i][3],
                        aB + (uint32_t)(i * 16 * ROWF * 4) + kk * 32);
                tfr(av[i][0]); tfr(av[i][1]); tfr(av[i][2]); tfr(av[i][3]);
            }
            uint32_t bv[4][4];
#pragma unroll
            for (int p = 0; p < 4; p++) {
                LDSM_X4(bv[p][0], bv[p][1], bv[p][2], bv[p][3],
                        bB + (uint32_t)(p * 16 * ROWF * 4) + kk * 32);
                tfr(bv[p][0]); tfr(bv[p][1]); tfr(bv[p][2]); tfr(bv[p][3]);
            }
#pragma unroll
            for (int i = 0; i < 4; i++)
#pragma unroll
                for (int p = 0; p < 4; p++) {
                    mma8(acc[i][2 * p],     av[i], &bv[p][0]);
                    mma8(acc[i][2 * p + 1], av[i], &bv[p][2]);
                }
        }
        buf++; if (buf >= NSTAGE) buf = 0;
    }
#undef LOAD_STAGE

    // ---- epilogue ----------------------------------------------------------
    const int cbase = ntile * BN + n_off + 2 * tig;
    float2 bv2[8];
#pragma unroll
    for (int j = 0; j < 8; j++) {
        bv2[j].x = bias[(size_t)e * NTOT + cbase + j * 8];
        bv2[j].y = bias[(size_t)e * NTOT + cbase + j * 8 + 1];
    }

#pragma unroll
    for (int i = 0; i < 4; i++) {
#pragma unroll
        for (int h = 0; h < 2; h++) {
            const int lrow = m_off + i * 16 + gid + h * 8;
            const int grow = mtile * BM + lrow;
            if (grow >= cnt) continue;
            if (FIRST) {
                float* dst = g_h + (size_t)(base + grow) * NTOT + cbase;
#pragma unroll
                for (int j = 0; j < 8; j++) {
                    float v0 = acc[i][j][h * 2]     + bv2[j].x;
                    float v1 = acc[i][j][h * 2 + 1] + bv2[j].y;
                    float g0 = 0.5f * v0 * (1.0f + erff(v0 * SQRT1_2));
                    float g1 = 0.5f * v1 * (1.0f + erff(v1 * SQRT1_2));
                    *reinterpret_cast<float2*>(dst + j * 8) =
                        make_float2(g0, g1);
                }
            } else {
                const int tok = g_slot_tok[base + grow];
                const float wt = g_slot_wt[base + grow];
                float* dst = out + (size_t)tok * NTOT + cbase;
#pragma unroll
                for (int j = 0; j < 8; j++) {
                    atomicAdd(dst + j * 8,
                              (acc[i][j][h * 2] + bv2[j].x) * wt);
                    atomicAdd(dst + j * 8 + 1,
                              (acc[i][j][h * 2 + 1] + bv2[j].y) * wt);
                }
            }
        }
    }
}

// ---------------- host launcher ---------------------------------------------
extern "C" void kernel_launch(void* const* d_in, const int* in_sizes, int n_in,
                              void* d_out, int out_size) {
    const float* x    = (const float*)d_in[0];
    const float* gate = (const float*)d_in[1];
    const float* w1   = (const float*)d_in[2];
    const float* b1   = (const float*)d_in[3];
    const float* w2   = (const float*)d_in[4];
    const float* b2   = (const float*)d_in[5];

    const int T = in_sizes[0] / HID;
    float* out = (float*)d_out;
    float* rlog = ((size_t)out_size >= (size_t)T * HID + (size_t)T * NEXP)
                      ? out + (size_t)T * HID : nullptr;

    cudaFuncSetAttribute(moe_gemm_kernel<HID, INTERD, true>,
                         cudaFuncAttributeMaxDynamicSharedMemorySize,
                         SMEM_BYTES);
    cudaFuncSetAttribute(moe_gemm_kernel<INTERD, HID, false>,
                         cudaFuncAttributeMaxDynamicSharedMemorySize,
                         SMEM_BYTES);

    cudaMemsetAsync(d_out, 0, (size_t)T * HID * sizeof(float));

    router_kernel<<<(T + 7) / 8, 256>>>(x, gate, rlog, T);
    count_kernel<<<64, 256>>>(T);
    compact_kernel<<<NEXP, 1024>>>(T);

    const int mtiles = (T + BM - 1) / BM;   // worst case: all tokens one expert
    moe_gemm_kernel<HID, INTERD, true>
        <<<dim3(INTERD / BN, mtiles, NEXP), 256, SMEM_BYTES>>>(
            x, w1, b1, nullptr);
    moe_gemm_kernel<INTERD, HID, false>
        <<<dim3(HID / BN, mtiles, NEXP), 256, SMEM_BYTES>>>(
            nullptr, w2, b2, out);
}